// round 15
// baseline (speedup 1.0000x reference)
#include <cuda_runtime.h>

#define NUM_BINS 15
#define NMC_CAP  10240
#define QB_CAP   80
#define DSPLIT   16
#define TILE     512
#define TPAIRS   (TILE / 2)
#define HTR_B    16
#define HTE_B    8
#define NCELL    25           /* 5x5 grid, cell size 2.0 over [-5,5] */
#define MAXCHUNK 640          /* >= ceil(20050/32) */
#define CUT2     3.2f         /* d^2 beyond which f16 exp2 is exactly 0 */

#define STEP (1.0f / 15.0f)
#define C2   (1.4426950408889634f / 0.18f)   /* log2e / (2*BW*BW) */
#define KN   (0.5654866776461628f)           /* 2*pi*BW*BW */
#define FULLM 0xffffffffu

typedef unsigned long long ull;

// ---------------- device scratch ----------------
__device__ int    g_hist_tr_p[HTR_B][NUM_BINS];
__device__ int    g_hist_te_p[HTE_B][NUM_BINS];
__device__ int    g_correct;
__device__ int    g_qcnt[NUM_BINS];
__device__ float2 g_q[NUM_BINS * NMC_CAP];
__device__ int    g_cs_tr[NCELL + 1];         // padded-even point offsets
__device__ int    g_cs_te[NCELL + 1];
__device__ float4 g_strx4[10240];             // sorted train points (pairs)
__device__ float4 g_stex4[5200];              // sorted test points (pairs)
// layout: [ (z*3 + ph)*NUM_BINS + bin ] * NMC_CAP + qi  (qi fastest: coalesced)
__device__ float  g_ssum[(size_t)DSPLIT * 3 * NUM_BINS * NMC_CAP];  // ~29 MB
__device__ float  g_part[NUM_BINS * QB_CAP];

// ---------------- packed helpers ----------------
#define ADD2(d, a, b)    asm("add.rn.f32x2 %0, %1, %2;"      : "=l"(d) : "l"(a), "l"(b))
#define FMA2(d, a, b, c) asm("fma.rn.f32x2 %0, %1, %2, %3;"  : "=l"(d) : "l"(a), "l"(b), "l"(c))
#define PK2(d, lo, hi)   asm("mov.b64 %0, {%1, %2};"         : "=l"(d) : "f"(lo), "f"(hi))
#define UPK2(lo, hi, s)  asm("mov.b64 {%0, %1}, %2;"         : "=f"(lo), "=f"(hi) : "l"(s))

__device__ __forceinline__ float ex2_approx(float x) {
    float r;
    asm("ex2.approx.ftz.f32 %0, %1;" : "=f"(r) : "f"(x));
    return r;
}

__device__ __forceinline__ int cell_of(float x, float y) {
    int cx = (int)floorf((x + 5.f) * 0.5f);
    int cy = (int)floorf((y + 5.f) * 0.5f);
    cx = min(4, max(0, cx));
    cy = min(4, max(0, cy));
    return cy * 5 + cx;
}

__device__ __forceinline__ bool pass_bin(float qx, float qy,
                                         const float* __restrict__ W,
                                         const float* __restrict__ bv,
                                         int bin) {
    float l[10];
    float lmax = -1e30f;
    #pragma unroll
    for (int c = 0; c < 10; c++) {
        l[c] = fmaf(qx, W[c], fmaf(qy, W[10 + c], bv[c]));
        lmax = fmaxf(lmax, l[c]);
    }
    float s = 0.f;
    #pragma unroll
    for (int c = 0; c < 10; c++) s += __expf(l[c] - lmax);
    float hs = 1.f / s;
    float lo = bin * STEP;
    float hi = (bin + 1) * STEP;
    return (hs >= lo) && (hs <= hi);
}

// ---------------- K1: filter+sort queries | sort data | hist | correct -------
__global__ void __launch_bounds__(1024) prep_kernel(
    const float* __restrict__ mc, const float* __restrict__ W,
    const float* __restrict__ bv,
    const float* __restrict__ trp, const float* __restrict__ tep,
    const float* __restrict__ trx, const float* __restrict__ tex,
    const int* __restrict__ y, const int* __restrict__ pred,
    int NMC, int NTR, int NTE, int B, int NTRX, int NTEX)
{
    __shared__ unsigned short scnt[NCELL][MAXCHUNK];  // 32000 B
    __shared__ unsigned char  scell[NMC_CAP];         // 10240 B
    __shared__ int            stot[NCELL];
    __shared__ int            scs[NCELL + 1];
    __shared__ int            red[1024];              // 4096 B

    const int part = blockIdx.x;
    const int tid  = threadIdx.x;
    const int lane = tid & 31;
    const int wid  = tid >> 5;

    if (part < NUM_BINS) {
        // ======== per-bin: filter by hat_s + stable sort by spatial cell =====
        const int bin = part;
        const int nchunk = (NMC + 31) / 32;
        const int nscan  = (nchunk + 31) / 32;        // uniform scan bound
        for (int i = tid; i < NCELL * MAXCHUNK; i += 1024)
            ((unsigned short*)scnt)[i] = 0;
        __syncthreads();

        // stage 1: classify + per-(cell,warpchunk) counts
        for (int base = 0; base < NMC; base += 1024) {
            int qi = base + tid;
            int cell = 255;
            if (qi < NMC) {
                float qx = mc[(size_t)(bin * NMC + qi) * 2 + 0];
                float qy = mc[(size_t)(bin * NMC + qi) * 2 + 1];
                if (pass_bin(qx, qy, W, bv, bin)) cell = cell_of(qx, qy);
            }
            if (qi < NMC_CAP) scell[qi] = (unsigned char)cell;
            unsigned peers = __match_any_sync(FULLM, cell);
            bool leader = (lane == (__ffs(peers) - 1));
            if (leader && cell < NCELL)
                scnt[cell][(base >> 5) + (tid >> 5)] = (unsigned short)__popc(peers);
        }
        __syncthreads();

        // stage 2: per-cell exclusive scan over chunks (warp per cell)
        if (wid < NCELL) {
            int carry = 0;
            for (int s = 0; s < nscan; s++) {         // uniform bound, no break
                int idx = s * 32 + lane;
                int v = (idx < nchunk) ? (int)scnt[wid][idx] : 0;
                int iv = v;
                #pragma unroll
                for (int o = 1; o < 32; o <<= 1) {
                    int t = __shfl_up_sync(FULLM, iv, o);
                    if (lane >= o) iv += t;
                }
                int tot = __shfl_sync(FULLM, iv, 31);
                if (idx < nchunk) scnt[wid][idx] = (unsigned short)(iv - v + carry);
                carry += tot;
            }
            if (lane == 0) stot[wid] = carry;
        }
        __syncthreads();
        if (tid == 0) {
            int run = 0;
            #pragma unroll
            for (int c = 0; c < NCELL; c++) { scs[c] = run; run += stot[c]; }
            scs[NCELL] = run;
            g_qcnt[bin] = run;
        }
        __syncthreads();

        // stage 3: stable scatter
        for (int base = 0; base < NMC; base += 1024) {
            int qi = base + tid;
            int cell = (qi < NMC) ? (int)scell[qi] : 255;
            unsigned peers = __match_any_sync(FULLM, cell);
            int rank = __popc(peers & ((1u << lane) - 1u));
            if (cell < NCELL) {
                float qx = mc[(size_t)(bin * NMC + qi) * 2 + 0];
                float qy = mc[(size_t)(bin * NMC + qi) * 2 + 1];
                int pos = scs[cell] + (int)scnt[cell][qi >> 5] + rank;
                g_q[bin * NMC_CAP + pos] = make_float2(qx, qy);
            }
        }
    } else if (part < NUM_BINS + 2) {
        // ======== data sort: stable counting sort by cell, even-padded =======
        const bool is_tr = (part == NUM_BINS);
        const float* src = is_tr ? trx : tex;
        const int    n   = is_tr ? NTRX : NTEX;
        float2* dst = is_tr ? (float2*)g_strx4 : (float2*)g_stex4;
        int*    gcs = is_tr ? g_cs_tr : g_cs_te;
        const int nchunk = (n + 31) / 32;
        const int nscan  = (nchunk + 31) / 32;

        for (int i = tid; i < NCELL * MAXCHUNK; i += 1024)
            ((unsigned short*)scnt)[i] = 0;
        __syncthreads();

        for (int base = 0; base < n; base += 1024) {
            int i = base + tid;
            int cell = 255;
            if (i < n)
                cell = cell_of(src[(size_t)i * 2], src[(size_t)i * 2 + 1]);
            unsigned peers = __match_any_sync(FULLM, cell);
            bool leader = (lane == (__ffs(peers) - 1));
            if (leader && cell < NCELL)
                scnt[cell][(base >> 5) + (tid >> 5)] = (unsigned short)__popc(peers);
        }
        __syncthreads();

        if (wid < NCELL) {
            int carry = 0;
            for (int s = 0; s < nscan; s++) {
                int idx = s * 32 + lane;
                int v = (idx < nchunk) ? (int)scnt[wid][idx] : 0;
                int iv = v;
                #pragma unroll
                for (int o = 1; o < 32; o <<= 1) {
                    int t = __shfl_up_sync(FULLM, iv, o);
                    if (lane >= o) iv += t;
                }
                int tot = __shfl_sync(FULLM, iv, 31);
                if (idx < nchunk) scnt[wid][idx] = (unsigned short)(iv - v + carry);
                carry += tot;
            }
            if (lane == 0) stot[wid] = carry;
        }
        __syncthreads();
        if (tid == 0) {
            int run = 0;
            #pragma unroll
            for (int c = 0; c < NCELL; c++) {
                scs[c] = run;
                run += stot[c] + (stot[c] & 1);   // pad to even
            }
            scs[NCELL] = run;
        }
        __syncthreads();

        for (int base = 0; base < n; base += 1024) {
            int i = base + tid;
            int cell = 255;
            float px = 0.f, py = 0.f;
            if (i < n) {
                px = src[(size_t)i * 2];
                py = src[(size_t)i * 2 + 1];
                cell = cell_of(px, py);
            }
            unsigned peers = __match_any_sync(FULLM, cell);
            int rank = __popc(peers & ((1u << lane) - 1u));
            if (cell < NCELL) {
                int pos = scs[cell] + (int)scnt[cell][i >> 5] + rank;
                dst[pos] = make_float2(px, py);
            }
        }
        __syncthreads();
        if (tid < NCELL && (stot[tid] & 1))     // sentinel fill for odd cells
            dst[scs[tid] + stot[tid]] = make_float2(1e3f, 1e3f);
        if (tid <= NCELL) gcs[tid] = scs[tid];
    } else if (part < NUM_BINS + 2 + HTR_B + HTE_B) {
        // ======== histogram partials =========================================
        __shared__ int sh[NUM_BINS];
        if (tid < NUM_BINS) sh[tid] = 0;
        __syncthreads();
        int hp = part - (NUM_BINS + 2);
        bool is_tr = (hp < HTR_B);
        const float* src = is_tr ? trp : tep;
        int n  = is_tr ? NTR : NTE;
        int nb = is_tr ? HTR_B : HTE_B;
        int pb = is_tr ? hp : hp - HTR_B;
        for (int i = pb * 1024 + tid; i < n; i += nb * 1024) {
            float p = src[i];
            int bx = (int)ceilf(p * 15.f) - 1;
            bx = min(14, max(0, bx));
            if (!(p > bx * STEP && p <= (bx + 1) * STEP)) {
                if (p <= bx * STEP) bx--; else bx++;
            }
            if (bx >= 0 && bx < NUM_BINS && p > bx * STEP && p <= (bx + 1) * STEP)
                atomicAdd(&sh[bx], 1);
        }
        __syncthreads();
        if (tid < NUM_BINS) {
            if (is_tr) g_hist_tr_p[pb][tid] = sh[tid];
            else       g_hist_te_p[pb][tid] = sh[tid];
        }
    } else {
        // ======== correct count ==============================================
        int c = 0;
        for (int i = tid; i < B; i += 1024)
            c += (y[i] == pred[i]) ? 1 : 0;
        red[tid] = c; __syncthreads();
        for (int s = 512; s > 0; s >>= 1) {
            if (tid < s) red[tid] += red[tid + s];
            __syncthreads();
        }
        if (tid == 0) g_correct = red[0];
    }
}

// ---------------- K2: KDE main with spatial cell culling ----------------
__global__ void __launch_bounds__(128) main_kernel(
    const float* __restrict__ bx,
    const int* __restrict__ y, const int* __restrict__ pred, int B)
{
    __shared__ __align__(16) unsigned char sraw[TILE * 16];
    float4* sP  = (float4*)sraw;
    float2* sZ  = (float2*)(sraw + TPAIRS * 16);
    float4* sd  = (float4*)sraw;
    __shared__ float4 wbb[4];   // per-warp bbox (xmin,ymin,xmax,ymax)

    const int bin = blockIdx.y;
    const int z   = blockIdx.z;
    const int cnt = g_qcnt[bin];
    if ((int)(blockIdx.x * 128) >= cnt) return;

    const int  qi  = blockIdx.x * 128 + threadIdx.x;
    const bool act = qi < cnt;
    float2 q = act ? g_q[bin * NMC_CAP + qi] : make_float2(0.f, 0.f);

    // block query bbox
    {
        float xmn = act ? q.x : 1e30f, xmx = act ? q.x : -1e30f;
        float ymn = act ? q.y : 1e30f, ymx = act ? q.y : -1e30f;
        #pragma unroll
        for (int o = 16; o > 0; o >>= 1) {
            xmn = fminf(xmn, __shfl_xor_sync(FULLM, xmn, o));
            xmx = fmaxf(xmx, __shfl_xor_sync(FULLM, xmx, o));
            ymn = fminf(ymn, __shfl_xor_sync(FULLM, ymn, o));
            ymx = fmaxf(ymx, __shfl_xor_sync(FULLM, ymx, o));
        }
        if ((threadIdx.x & 31) == 0)
            wbb[threadIdx.x >> 5] = make_float4(xmn, ymn, xmx, ymx);
    }
    __syncthreads();
    float bxmin = 1e30f, bymin = 1e30f, bxmax = -1e30f, bymax = -1e30f;
    #pragma unroll
    for (int w = 0; w < 4; w++) {
        float4 b = wbb[w];
        bxmin = fminf(bxmin, b.x); bymin = fminf(bymin, b.y);
        bxmax = fmaxf(bxmax, b.z); bymax = fmaxf(bymax, b.w);
    }

    const float Cm = 2.f * C2;
    const float A  = -C2 * (q.x * q.x + q.y * q.y);
    ull qx2, qy2, A2;
    PK2(qx2, q.x, q.x);
    PK2(qy2, q.y, q.y);
    PK2(A2,  A,   A);

    // ---- phases 0/1: unweighted KDE over sorted data with cell culling ----
    #pragma unroll 1
    for (int ph = 0; ph < 2; ph++) {
        const float4* src4 = (ph == 0) ? g_strx4 : g_stex4;
        const int*    cs   = (ph == 0) ? g_cs_tr : g_cs_te;
        float a0 = 0.f, a1 = 0.f;

        #pragma unroll 1
        for (int c = 0; c < NCELL; c++) {
            float rx0 = (float)(c % 5) * 2.f - 5.f;
            float ry0 = (float)(c / 5) * 2.f - 5.f;
            float ddx = fmaxf(fmaxf(rx0 - bxmax, bxmin - (rx0 + 2.f)), 0.f);
            float ddy = fmaxf(fmaxf(ry0 - bymax, bymin - (ry0 + 2.f)), 0.f);
            if (ddx * ddx + ddy * ddy > CUT2) continue;   // block-uniform branch

            int P0 = cs[c] >> 1, P1 = cs[c + 1] >> 1;
            int np = P1 - P0;
            int z0 = P0 + np * z / DSPLIT;
            int z1 = P0 + np * (z + 1) / DSPLIT;

            for (int basep = z0; basep < z1; basep += TPAIRS) {
                int mp = min(TPAIRS, z1 - basep);
                for (int jp = threadIdx.x; jp < mp; jp += 128) {
                    float4 v = src4[basep + jp];          // (x0,y0,x1,y1)
                    sP[jp] = make_float4(Cm * v.x, Cm * v.z, Cm * v.y, Cm * v.w);
                    sZ[jp] = make_float2(-C2 * (v.x * v.x + v.y * v.y),
                                         -C2 * (v.z * v.z + v.w * v.w));
                }
                __syncthreads();

                unsigned hacc = 0u;
                #pragma unroll 16
                for (int jp = 0; jp < mp; jp++) {
                    ulonglong2 pp = ((const ulonglong2*)sP)[jp];
                    ull pz = ((const ull*)sZ)[jp];
                    ull t;
                    ADD2(t, pz, A2);
                    FMA2(t, pp.y, qy2, t);
                    FMA2(t, pp.x, qx2, t);
                    float f0, f1;
                    UPK2(f0, f1, t);
                    unsigned h, e;
                    asm("cvt.rn.f16x2.f32 %0, %1, %2;" : "=r"(h) : "f"(f1), "f"(f0));
                    asm("ex2.approx.f16x2 %0, %1;" : "=r"(e) : "r"(h));
                    asm("add.rn.f16x2 %0, %1, %2;" : "=r"(hacc) : "r"(hacc), "r"(e));
                    if ((jp & 15) == 15) {
                        float g0, g1;
                        asm("{.reg .b16 lo,hi; mov.b32 {lo,hi}, %2;"
                            " cvt.f32.f16 %0, lo; cvt.f32.f16 %1, hi;}"
                            : "=f"(g0), "=f"(g1) : "r"(hacc));
                        a0 += g0; a1 += g1; hacc = 0u;
                    }
                }
                {
                    float g0, g1;
                    asm("{.reg .b16 lo,hi; mov.b32 {lo,hi}, %2;"
                        " cvt.f32.f16 %0, lo; cvt.f32.f16 %1, hi;}"
                        : "=f"(g0), "=f"(g1) : "r"(hacc));
                    a0 += g0; a1 += g1;
                }
                __syncthreads();
            }
        }
        if (act)
            g_ssum[((size_t)(z * 3 + ph) * NUM_BINS + bin) * NMC_CAP + qi] = a0 + a1;
    }

    // ---- phase 2: weighted KDE over batch (small), exact fp32 ----
    {
        const int np = B / 2;
        const int i0 = 2 * (np * z / DSPLIT);
        const int i1 = 2 * (np * (z + 1) / DSPLIT);
        float a0 = 0.f, a1 = 0.f;

        for (int base = i0; base < i1; base += TILE) {
            int m = min(TILE, i1 - base);
            for (int j = threadIdx.x; j < m; j += 128) {
                float dx = bx[(size_t)(base + j) * 2 + 0];
                float dy = bx[(size_t)(base + j) * 2 + 1];
                float wt = (y[base + j] == pred[base + j]) ? 1.f : 0.f;
                sd[j] = make_float4(Cm * dx, Cm * dy,
                                    -C2 * (dx * dx + dy * dy), wt);
            }
            __syncthreads();
            #pragma unroll 8
            for (int j = 0; j < m; j++) {
                float4 p = sd[j];
                float arg = fmaf(p.x, q.x, fmaf(p.y, q.y, p.z + A));
                float e = ex2_approx(arg);
                if (j & 1) a1 = fmaf(e, p.w, a1);
                else       a0 = fmaf(e, p.w, a0);
            }
            __syncthreads();
        }
        if (act)
            g_ssum[((size_t)(z * 3 + 2) * NUM_BINS + bin) * NMC_CAP + qi] = a0 + a1;
    }
}

// ---------------- K3: combine partials -> per-block v sums ----------------
__global__ void __launch_bounds__(128) combine_kernel(int NTRX, int NTEX, int B,
                                                      int NTR, int NTE)
{
    __shared__ float red[128];
    const int bin = blockIdx.y;
    const int cnt = g_qcnt[bin];
    const int qi  = blockIdx.x * 128 + threadIdx.x;

    float v = 0.f;
    if (qi < cnt) {
        float s0 = 0.f, s1 = 0.f, s2 = 0.f;
        #pragma unroll
        for (int zz = 0; zz < DSPLIT; zz++) {
            s0 += g_ssum[((size_t)(zz * 3 + 0) * NUM_BINS + bin) * NMC_CAP + qi];
            s1 += g_ssum[((size_t)(zz * 3 + 1) * NUM_BINS + bin) * NMC_CAP + qi];
            s2 += g_ssum[((size_t)(zz * 3 + 2) * NUM_BINS + bin) * NMC_CAP + qi];
        }
        int htr = 0, hte = 0;
        #pragma unroll
        for (int k = 0; k < HTR_B; k++) htr += g_hist_tr_p[k][bin];
        #pragma unroll
        for (int k = 0; k < HTE_B; k++) hte += g_hist_te_p[k][bin];
        float trr = (float)htr / (float)NTR;
        float ter = (float)hte / (float)NTE;
        float cntf = (float)g_correct;

        float kde_tr = s0 / ((float)NTRX * KN);
        float kde_te = s1 / ((float)NTEX * KN);
        float kde_w  = s2 / (fmaxf(cntf, 1.f) * KN);
        float p_y    = cntf / (float)B;

        float d_t = (ter > 0.f) ? (kde_te / ter) : 0.f;
        float d_s = (trr > 0.f) ? (kde_tr / trr) : 0.f;

        float p_hs = kde_w * p_y / (kde_tr + 1e-8f);
        p_hs = fminf(fmaxf(p_hs, 0.f), 1.f);
        v = p_hs * (d_t - d_s);
    }

    red[threadIdx.x] = v; __syncthreads();
    for (int s = 64; s > 0; s >>= 1) {
        if (threadIdx.x < s) red[threadIdx.x] += red[threadIdx.x + s];
        __syncthreads();
    }
    if (threadIdx.x == 0)
        g_part[bin * QB_CAP + blockIdx.x] = red[0];
}

// ---------------- K4: final (one warp per bin, parallel) ----------------
__global__ void __launch_bounds__(NUM_BINS * 32) final_kernel(
    float* __restrict__ out, int nqb, int NMC, int NTE)
{
    __shared__ float sbin[NUM_BINS];
    const int bin  = threadIdx.x >> 5;
    const int lane = threadIdx.x & 31;

    float s = 0.f;
    for (int j = lane; j < nqb; j += 32) s += g_part[bin * QB_CAP + j];
    #pragma unroll
    for (int o = 16; o > 0; o >>= 1) s += __shfl_xor_sync(0xffffffff, s, o);

    if (lane == 0) {
        int hte = 0;
        #pragma unroll
        for (int k = 0; k < HTE_B; k++) hte += g_hist_te_p[k][bin];
        float ter = (float)hte / (float)NTE;
        float integral = (s / (float)NMC) * 100.0f;
        sbin[bin] = (ter > 0.f) ? ter * fabsf(integral) : 0.f;
    }
    __syncthreads();
    if (threadIdx.x == 0) {
        float ec = 0.f;
        #pragma unroll
        for (int b = 0; b < NUM_BINS; b++) ec += sbin[b];
        out[0] = ec;
    }
}

// ---------------- launch ----------------
extern "C" void kernel_launch(void* const* d_in, const int* in_sizes, int n_in,
                              void* d_out, int out_size)
{
    const float* bx   = (const float*)d_in[0];
    const int*   y    = (const int*)  d_in[1];
    const int*   pred = (const int*)  d_in[2];
    const float* trp  = (const float*)d_in[3];
    const float* tep  = (const float*)d_in[4];
    const float* trx  = (const float*)d_in[5];
    const float* tex  = (const float*)d_in[6];
    const float* W    = (const float*)d_in[7];
    const float* bv   = (const float*)d_in[8];
    const float* mc   = (const float*)d_in[9];

    int B    = in_sizes[1];
    int NTR  = in_sizes[3];
    int NTE  = in_sizes[4];
    int NTRX = in_sizes[5] / 2;
    int NTEX = in_sizes[6] / 2;
    int NMC  = in_sizes[9] / (2 * NUM_BINS);
    int nqb  = (NMC + 127) / 128;

    prep_kernel<<<NUM_BINS + 2 + HTR_B + HTE_B + 1, 1024>>>(
        mc, W, bv, trp, tep, trx, tex, y, pred,
        NMC, NTR, NTE, B, NTRX, NTEX);

    dim3 mg(nqb, NUM_BINS, DSPLIT);
    main_kernel<<<mg, 128>>>(bx, y, pred, B);

    dim3 cg(nqb, NUM_BINS);
    combine_kernel<<<cg, 128>>>(NTRX, NTEX, B, NTR, NTE);

    final_kernel<<<1, NUM_BINS * 32>>>((float*)d_out, nqb, NMC, NTE);
}

// round 16
// speedup vs baseline: 1.1956x; 1.1956x over previous
#include <cuda_runtime.h>

#define NUM_BINS 15
#define NMC_CAP  10240
#define QB_CAP   80
#define DSPLIT   32
#define TILE     512
#define TPAIRS   (TILE / 2)
#define HTR_B    16
#define HTE_B    8
#define NCELL    25           /* 5x5 grid, cell size 2.0 over [-5,5] */
#define MAXCHUNK 640
#define MAXT     48           /* max 256-pair tiles per dataset */
#define CUT2     3.2f         /* d^2 beyond which f16 exp2 is exactly 0 */

#define STEP (1.0f / 15.0f)
#define C2   (1.4426950408889634f / 0.18f)
#define KN   (0.5654866776461628f)
#define FULLM 0xffffffffu

typedef unsigned long long ull;

// ---------------- device scratch ----------------
__device__ int    g_hist_tr_p[HTR_B][NUM_BINS];
__device__ int    g_hist_te_p[HTE_B][NUM_BINS];
__device__ int    g_correct;
__device__ int    g_qcnt[NUM_BINS];
__device__ float2 g_q[NUM_BINS * NMC_CAP];
__device__ int    g_npair[2];                 // padded pair counts (tr, te)
__device__ float4 g_tbb_tr[MAXT];             // per-tile bbox (xmin,ymin,xmax,ymax)
__device__ float4 g_tbb_te[MAXT];
__device__ float4 g_strx4[10240];             // sorted train pairs
__device__ float4 g_stex4[5200];              // sorted test pairs
// layout: [ (z*3 + ph)*NUM_BINS + bin ] * NMC_CAP + qi  (qi fastest: coalesced)
__device__ float  g_ssum[(size_t)DSPLIT * 3 * NUM_BINS * NMC_CAP];  // ~59 MB
__device__ float  g_part[NUM_BINS * QB_CAP];

// ---------------- packed helpers ----------------
#define ADD2(d, a, b)    asm("add.rn.f32x2 %0, %1, %2;"      : "=l"(d) : "l"(a), "l"(b))
#define FMA2(d, a, b, c) asm("fma.rn.f32x2 %0, %1, %2, %3;"  : "=l"(d) : "l"(a), "l"(b), "l"(c))
#define PK2(d, lo, hi)   asm("mov.b64 %0, {%1, %2};"         : "=l"(d) : "f"(lo), "f"(hi))
#define UPK2(lo, hi, s)  asm("mov.b64 {%0, %1}, %2;"         : "=f"(lo), "=f"(hi) : "l"(s))

__device__ __forceinline__ float ex2_approx(float x) {
    float r;
    asm("ex2.approx.ftz.f32 %0, %1;" : "=f"(r) : "f"(x));
    return r;
}

__device__ __forceinline__ int cell_of(float x, float y) {
    int cx = (int)floorf((x + 5.f) * 0.5f);
    int cy = (int)floorf((y + 5.f) * 0.5f);
    cx = min(4, max(0, cx));
    cy = min(4, max(0, cy));
    return cy * 5 + cx;
}

__device__ __forceinline__ bool pass_bin(float qx, float qy,
                                         const float* __restrict__ W,
                                         const float* __restrict__ bv,
                                         int bin) {
    float l[10];
    float lmax = -1e30f;
    #pragma unroll
    for (int c = 0; c < 10; c++) {
        l[c] = fmaf(qx, W[c], fmaf(qy, W[10 + c], bv[c]));
        lmax = fmaxf(lmax, l[c]);
    }
    float s = 0.f;
    #pragma unroll
    for (int c = 0; c < 10; c++) s += __expf(l[c] - lmax);
    float hs = 1.f / s;
    float lo = bin * STEP;
    float hi = (bin + 1) * STEP;
    return (hs >= lo) && (hs <= hi);
}

// ---------------- K1: filter+sort queries | sort data+tile bbox | hist -------
__global__ void __launch_bounds__(1024) prep_kernel(
    const float* __restrict__ mc, const float* __restrict__ W,
    const float* __restrict__ bv,
    const float* __restrict__ trp, const float* __restrict__ tep,
    const float* __restrict__ trx, const float* __restrict__ tex,
    const int* __restrict__ y, const int* __restrict__ pred,
    int NMC, int NTR, int NTE, int B, int NTRX, int NTEX)
{
    __shared__ unsigned short scnt[NCELL][MAXCHUNK];
    __shared__ unsigned char  scell[NMC_CAP];
    __shared__ int            stot[NCELL];
    __shared__ int            scs[NCELL + 1];
    __shared__ int            red[1024];

    const int part = blockIdx.x;
    const int tid  = threadIdx.x;
    const int lane = tid & 31;
    const int wid  = tid >> 5;

    if (part < NUM_BINS) {
        // ---- per-bin: filter by hat_s + stable sort by spatial cell ----
        const int bin = part;
        const int nchunk = (NMC + 31) / 32;
        const int nscan  = (nchunk + 31) / 32;
        for (int i = tid; i < NCELL * MAXCHUNK; i += 1024)
            ((unsigned short*)scnt)[i] = 0;
        __syncthreads();

        for (int base = 0; base < NMC; base += 1024) {
            int qi = base + tid;
            int cell = 255;
            if (qi < NMC) {
                float qx = mc[(size_t)(bin * NMC + qi) * 2 + 0];
                float qy = mc[(size_t)(bin * NMC + qi) * 2 + 1];
                if (pass_bin(qx, qy, W, bv, bin)) cell = cell_of(qx, qy);
            }
            if (qi < NMC_CAP) scell[qi] = (unsigned char)cell;
            unsigned peers = __match_any_sync(FULLM, cell);
            bool leader = (lane == (__ffs(peers) - 1));
            if (leader && cell < NCELL)
                scnt[cell][(base >> 5) + (tid >> 5)] = (unsigned short)__popc(peers);
        }
        __syncthreads();

        if (wid < NCELL) {
            int carry = 0;
            for (int s = 0; s < nscan; s++) {
                int idx = s * 32 + lane;
                int v = (idx < nchunk) ? (int)scnt[wid][idx] : 0;
                int iv = v;
                #pragma unroll
                for (int o = 1; o < 32; o <<= 1) {
                    int t = __shfl_up_sync(FULLM, iv, o);
                    if (lane >= o) iv += t;
                }
                int tot = __shfl_sync(FULLM, iv, 31);
                if (idx < nchunk) scnt[wid][idx] = (unsigned short)(iv - v + carry);
                carry += tot;
            }
            if (lane == 0) stot[wid] = carry;
        }
        __syncthreads();
        if (tid == 0) {
            int run = 0;
            #pragma unroll
            for (int c = 0; c < NCELL; c++) { scs[c] = run; run += stot[c]; }
            scs[NCELL] = run;
            g_qcnt[bin] = run;
        }
        __syncthreads();

        for (int base = 0; base < NMC; base += 1024) {
            int qi = base + tid;
            int cell = (qi < NMC) ? (int)scell[qi] : 255;
            unsigned peers = __match_any_sync(FULLM, cell);
            int rank = __popc(peers & ((1u << lane) - 1u));
            if (cell < NCELL) {
                float qx = mc[(size_t)(bin * NMC + qi) * 2 + 0];
                float qy = mc[(size_t)(bin * NMC + qi) * 2 + 1];
                int pos = scs[cell] + (int)scnt[cell][qi >> 5] + rank;
                g_q[bin * NMC_CAP + pos] = make_float2(qx, qy);
            }
        }
    } else if (part < NUM_BINS + 2) {
        // ---- data sort: stable counting sort by cell + per-tile bbox ----
        const bool is_tr = (part == NUM_BINS);
        const float* src = is_tr ? trx : tex;
        const int    n   = is_tr ? NTRX : NTEX;
        float2* dst = is_tr ? (float2*)g_strx4 : (float2*)g_stex4;
        float4* tbb = is_tr ? g_tbb_tr : g_tbb_te;
        const int nchunk = (n + 31) / 32;
        const int nscan  = (nchunk + 31) / 32;

        for (int i = tid; i < NCELL * MAXCHUNK; i += 1024)
            ((unsigned short*)scnt)[i] = 0;
        __syncthreads();

        for (int base = 0; base < n; base += 1024) {
            int i = base + tid;
            int cell = 255;
            if (i < n)
                cell = cell_of(src[(size_t)i * 2], src[(size_t)i * 2 + 1]);
            unsigned peers = __match_any_sync(FULLM, cell);
            bool leader = (lane == (__ffs(peers) - 1));
            if (leader && cell < NCELL)
                scnt[cell][(base >> 5) + (tid >> 5)] = (unsigned short)__popc(peers);
        }
        __syncthreads();

        if (wid < NCELL) {
            int carry = 0;
            for (int s = 0; s < nscan; s++) {
                int idx = s * 32 + lane;
                int v = (idx < nchunk) ? (int)scnt[wid][idx] : 0;
                int iv = v;
                #pragma unroll
                for (int o = 1; o < 32; o <<= 1) {
                    int t = __shfl_up_sync(FULLM, iv, o);
                    if (lane >= o) iv += t;
                }
                int tot = __shfl_sync(FULLM, iv, 31);
                if (idx < nchunk) scnt[wid][idx] = (unsigned short)(iv - v + carry);
                carry += tot;
            }
            if (lane == 0) stot[wid] = carry;
        }
        __syncthreads();
        if (tid == 0) {
            int run = 0;
            #pragma unroll
            for (int c = 0; c < NCELL; c++) {
                scs[c] = run;
                run += stot[c] + (stot[c] & 1);   // pad to even
            }
            scs[NCELL] = run;
            g_npair[is_tr ? 0 : 1] = run >> 1;
        }
        __syncthreads();

        for (int base = 0; base < n; base += 1024) {
            int i = base + tid;
            int cell = 255;
            float px = 0.f, py = 0.f;
            if (i < n) {
                px = src[(size_t)i * 2];
                py = src[(size_t)i * 2 + 1];
                cell = cell_of(px, py);
            }
            unsigned peers = __match_any_sync(FULLM, cell);
            int rank = __popc(peers & ((1u << lane) - 1u));
            if (cell < NCELL) {
                int pos = scs[cell] + (int)scnt[cell][i >> 5] + rank;
                dst[pos] = make_float2(px, py);
            }
        }
        __syncthreads();
        if (tid < NCELL && (stot[tid] & 1))
            dst[scs[tid] + stot[tid]] = make_float2(1e3f, 1e3f);
        __syncthreads();

        // per-tile bbox (TILE points per tile), excluding sentinels
        {
            int npts = scs[NCELL];
            int nt = (npts + TILE - 1) / TILE;
            for (int t = wid; t < nt; t += 32) {
                int j0 = t * TILE;
                int j1 = min(j0 + TILE, npts);
                float xmn = 1e30f, xmx = -1e30f, ymn = 1e30f, ymx = -1e30f;
                for (int j = j0 + lane; j < j1; j += 32) {
                    float2 p = dst[j];
                    if (p.x < 900.f) {
                        xmn = fminf(xmn, p.x); xmx = fmaxf(xmx, p.x);
                        ymn = fminf(ymn, p.y); ymx = fmaxf(ymx, p.y);
                    }
                }
                #pragma unroll
                for (int o = 16; o > 0; o >>= 1) {
                    xmn = fminf(xmn, __shfl_xor_sync(FULLM, xmn, o));
                    xmx = fmaxf(xmx, __shfl_xor_sync(FULLM, xmx, o));
                    ymn = fminf(ymn, __shfl_xor_sync(FULLM, ymn, o));
                    ymx = fmaxf(ymx, __shfl_xor_sync(FULLM, ymx, o));
                }
                if (lane == 0) tbb[t] = make_float4(xmn, ymn, xmx, ymx);
            }
        }
    } else if (part < NUM_BINS + 2 + HTR_B + HTE_B) {
        __shared__ int sh[NUM_BINS];
        if (tid < NUM_BINS) sh[tid] = 0;
        __syncthreads();
        int hp = part - (NUM_BINS + 2);
        bool is_tr = (hp < HTR_B);
        const float* src = is_tr ? trp : tep;
        int n  = is_tr ? NTR : NTE;
        int nb = is_tr ? HTR_B : HTE_B;
        int pb = is_tr ? hp : hp - HTR_B;
        for (int i = pb * 1024 + tid; i < n; i += nb * 1024) {
            float p = src[i];
            int bx = (int)ceilf(p * 15.f) - 1;
            bx = min(14, max(0, bx));
            if (!(p > bx * STEP && p <= (bx + 1) * STEP)) {
                if (p <= bx * STEP) bx--; else bx++;
            }
            if (bx >= 0 && bx < NUM_BINS && p > bx * STEP && p <= (bx + 1) * STEP)
                atomicAdd(&sh[bx], 1);
        }
        __syncthreads();
        if (tid < NUM_BINS) {
            if (is_tr) g_hist_tr_p[pb][tid] = sh[tid];
            else       g_hist_te_p[pb][tid] = sh[tid];
        }
    } else {
        int c = 0;
        for (int i = tid; i < B; i += 1024)
            c += (y[i] == pred[i]) ? 1 : 0;
        red[tid] = c; __syncthreads();
        for (int s = 512; s > 0; s >>= 1) {
            if (tid < s) red[tid] += red[tid + s];
            __syncthreads();
        }
        if (tid == 0) g_correct = red[0];
    }
}

// ---------------- K2: KDE main with per-tile bbox culling ----------------
__global__ void __launch_bounds__(128) main_kernel(
    const float* __restrict__ bx,
    const int* __restrict__ y, const int* __restrict__ pred, int B)
{
    __shared__ __align__(16) unsigned char sraw[TILE * 16];
    float4* sP  = (float4*)sraw;
    float2* sZ  = (float2*)(sraw + TPAIRS * 16);
    float4* sd  = (float4*)sraw;
    __shared__ float4 wbb[4];

    const int bin = blockIdx.y;
    const int z   = blockIdx.z;
    const int cnt = g_qcnt[bin];
    if ((int)(blockIdx.x * 128) >= cnt) return;

    const int  qi  = blockIdx.x * 128 + threadIdx.x;
    const bool act = qi < cnt;
    float2 q = act ? g_q[bin * NMC_CAP + qi] : make_float2(0.f, 0.f);

    // block query bbox
    {
        float xmn = act ? q.x : 1e30f, xmx = act ? q.x : -1e30f;
        float ymn = act ? q.y : 1e30f, ymx = act ? q.y : -1e30f;
        #pragma unroll
        for (int o = 16; o > 0; o >>= 1) {
            xmn = fminf(xmn, __shfl_xor_sync(FULLM, xmn, o));
            xmx = fmaxf(xmx, __shfl_xor_sync(FULLM, xmx, o));
            ymn = fminf(ymn, __shfl_xor_sync(FULLM, ymn, o));
            ymx = fmaxf(ymx, __shfl_xor_sync(FULLM, ymx, o));
        }
        if ((threadIdx.x & 31) == 0)
            wbb[threadIdx.x >> 5] = make_float4(xmn, ymn, xmx, ymx);
    }
    __syncthreads();
    float bxmin = 1e30f, bymin = 1e30f, bxmax = -1e30f, bymax = -1e30f;
    #pragma unroll
    for (int w = 0; w < 4; w++) {
        float4 b = wbb[w];
        bxmin = fminf(bxmin, b.x); bymin = fminf(bymin, b.y);
        bxmax = fmaxf(bxmax, b.z); bymax = fmaxf(bymax, b.w);
    }

    const float Cm = 2.f * C2;
    const float A  = -C2 * (q.x * q.x + q.y * q.y);
    ull qx2, qy2, A2;
    PK2(qx2, q.x, q.x);
    PK2(qy2, q.y, q.y);
    PK2(A2,  A,   A);

    // ---- phases 0/1: tile loop with bbox cull ----
    #pragma unroll 1
    for (int ph = 0; ph < 2; ph++) {
        const float4* src4 = (ph == 0) ? g_strx4 : g_stex4;
        const float4* tbb  = (ph == 0) ? g_tbb_tr : g_tbb_te;
        const int npair = g_npair[ph];
        const int nt = (npair + TPAIRS - 1) / TPAIRS;
        const int t0 = (int)(((long long)z * nt) / DSPLIT);
        const int t1 = (int)(((long long)(z + 1) * nt) / DSPLIT);
        float a0 = 0.f, a1 = 0.f;

        #pragma unroll 1
        for (int t = t0; t < t1; t++) {
            float4 bb = tbb[t];   // (xmin,ymin,xmax,ymax), block-uniform
            float ddx = fmaxf(fmaxf(bb.x - bxmax, bxmin - bb.z), 0.f);
            float ddy = fmaxf(fmaxf(bb.y - bymax, bymin - bb.w), 0.f);
            if (ddx * ddx + ddy * ddy > CUT2) continue;   // uniform skip

            int basep = t * TPAIRS;
            int mp = min(TPAIRS, npair - basep);
            for (int jp = threadIdx.x; jp < mp; jp += 128) {
                float4 v = src4[basep + jp];
                sP[jp] = make_float4(Cm * v.x, Cm * v.z, Cm * v.y, Cm * v.w);
                sZ[jp] = make_float2(-C2 * (v.x * v.x + v.y * v.y),
                                     -C2 * (v.z * v.z + v.w * v.w));
            }
            __syncthreads();

            unsigned hacc = 0u;
            #pragma unroll 16
            for (int jp = 0; jp < mp; jp++) {
                ulonglong2 pp = ((const ulonglong2*)sP)[jp];
                ull pz = ((const ull*)sZ)[jp];
                ull tt;
                ADD2(tt, pz, A2);
                FMA2(tt, pp.y, qy2, tt);
                FMA2(tt, pp.x, qx2, tt);
                float f0, f1;
                UPK2(f0, f1, tt);
                unsigned h, e;
                asm("cvt.rn.f16x2.f32 %0, %1, %2;" : "=r"(h) : "f"(f1), "f"(f0));
                asm("ex2.approx.f16x2 %0, %1;" : "=r"(e) : "r"(h));
                asm("add.rn.f16x2 %0, %1, %2;" : "=r"(hacc) : "r"(hacc), "r"(e));
                if ((jp & 15) == 15) {
                    float g0, g1;
                    asm("{.reg .b16 lo,hi; mov.b32 {lo,hi}, %2;"
                        " cvt.f32.f16 %0, lo; cvt.f32.f16 %1, hi;}"
                        : "=f"(g0), "=f"(g1) : "r"(hacc));
                    a0 += g0; a1 += g1; hacc = 0u;
                }
            }
            {
                float g0, g1;
                asm("{.reg .b16 lo,hi; mov.b32 {lo,hi}, %2;"
                    " cvt.f32.f16 %0, lo; cvt.f32.f16 %1, hi;}"
                    : "=f"(g0), "=f"(g1) : "r"(hacc));
                a0 += g0; a1 += g1;
            }
            __syncthreads();
        }
        if (act)
            g_ssum[((size_t)(z * 3 + ph) * NUM_BINS + bin) * NMC_CAP + qi] = a0 + a1;
    }

    // ---- phase 2: weighted KDE over batch, exact fp32 ----
    {
        const int np = B / 2;
        const int i0 = 2 * (np * z / DSPLIT);
        const int i1 = 2 * (np * (z + 1) / DSPLIT);
        float a0 = 0.f, a1 = 0.f;

        for (int base = i0; base < i1; base += TILE) {
            int m = min(TILE, i1 - base);
            for (int j = threadIdx.x; j < m; j += 128) {
                float dx = bx[(size_t)(base + j) * 2 + 0];
                float dy = bx[(size_t)(base + j) * 2 + 1];
                float wt = (y[base + j] == pred[base + j]) ? 1.f : 0.f;
                sd[j] = make_float4(Cm * dx, Cm * dy,
                                    -C2 * (dx * dx + dy * dy), wt);
            }
            __syncthreads();
            #pragma unroll 8
            for (int j = 0; j < m; j++) {
                float4 p = sd[j];
                float arg = fmaf(p.x, q.x, fmaf(p.y, q.y, p.z + A));
                float e = ex2_approx(arg);
                if (j & 1) a1 = fmaf(e, p.w, a1);
                else       a0 = fmaf(e, p.w, a0);
            }
            __syncthreads();
        }
        if (act)
            g_ssum[((size_t)(z * 3 + 2) * NUM_BINS + bin) * NMC_CAP + qi] = a0 + a1;
    }
}

// ---------------- K3: combine partials -> per-block v sums ----------------
__global__ void __launch_bounds__(128) combine_kernel(int NTRX, int NTEX, int B,
                                                      int NTR, int NTE)
{
    __shared__ float red[128];
    const int bin = blockIdx.y;
    const int cnt = g_qcnt[bin];
    const int qi  = blockIdx.x * 128 + threadIdx.x;

    float v = 0.f;
    if (qi < cnt) {
        float s0 = 0.f, s1 = 0.f, s2 = 0.f;
        #pragma unroll
        for (int zz = 0; zz < DSPLIT; zz++) {
            s0 += g_ssum[((size_t)(zz * 3 + 0) * NUM_BINS + bin) * NMC_CAP + qi];
            s1 += g_ssum[((size_t)(zz * 3 + 1) * NUM_BINS + bin) * NMC_CAP + qi];
            s2 += g_ssum[((size_t)(zz * 3 + 2) * NUM_BINS + bin) * NMC_CAP + qi];
        }
        int htr = 0, hte = 0;
        #pragma unroll
        for (int k = 0; k < HTR_B; k++) htr += g_hist_tr_p[k][bin];
        #pragma unroll
        for (int k = 0; k < HTE_B; k++) hte += g_hist_te_p[k][bin];
        float trr = (float)htr / (float)NTR;
        float ter = (float)hte / (float)NTE;
        float cntf = (float)g_correct;

        float kde_tr = s0 / ((float)NTRX * KN);
        float kde_te = s1 / ((float)NTEX * KN);
        float kde_w  = s2 / (fmaxf(cntf, 1.f) * KN);
        float p_y    = cntf / (float)B;

        float d_t = (ter > 0.f) ? (kde_te / ter) : 0.f;
        float d_s = (trr > 0.f) ? (kde_tr / trr) : 0.f;

        float p_hs = kde_w * p_y / (kde_tr + 1e-8f);
        p_hs = fminf(fmaxf(p_hs, 0.f), 1.f);
        v = p_hs * (d_t - d_s);
    }

    red[threadIdx.x] = v; __syncthreads();
    for (int s = 64; s > 0; s >>= 1) {
        if (threadIdx.x < s) red[threadIdx.x] += red[threadIdx.x + s];
        __syncthreads();
    }
    if (threadIdx.x == 0)
        g_part[bin * QB_CAP + blockIdx.x] = red[0];
}

// ---------------- K4: final (one warp per bin, parallel) ----------------
__global__ void __launch_bounds__(NUM_BINS * 32) final_kernel(
    float* __restrict__ out, int nqb, int NMC, int NTE)
{
    __shared__ float sbin[NUM_BINS];
    const int bin  = threadIdx.x >> 5;
    const int lane = threadIdx.x & 31;

    float s = 0.f;
    for (int j = lane; j < nqb; j += 32) s += g_part[bin * QB_CAP + j];
    #pragma unroll
    for (int o = 16; o > 0; o >>= 1) s += __shfl_xor_sync(0xffffffff, s, o);

    if (lane == 0) {
        int hte = 0;
        #pragma unroll
        for (int k = 0; k < HTE_B; k++) hte += g_hist_te_p[k][bin];
        float ter = (float)hte / (float)NTE;
        float integral = (s / (float)NMC) * 100.0f;
        sbin[bin] = (ter > 0.f) ? ter * fabsf(integral) : 0.f;
    }
    __syncthreads();
    if (threadIdx.x == 0) {
        float ec = 0.f;
        #pragma unroll
        for (int b = 0; b < NUM_BINS; b++) ec += sbin[b];
        out[0] = ec;
    }
}

// ---------------- launch ----------------
extern "C" void kernel_launch(void* const* d_in, const int* in_sizes, int n_in,
                              void* d_out, int out_size)
{
    const float* bx   = (const float*)d_in[0];
    const int*   y    = (const int*)  d_in[1];
    const int*   pred = (const int*)  d_in[2];
    const float* trp  = (const float*)d_in[3];
    const float* tep  = (const float*)d_in[4];
    const float* trx  = (const float*)d_in[5];
    const float* tex  = (const float*)d_in[6];
    const float* W    = (const float*)d_in[7];
    const float* bv   = (const float*)d_in[8];
    const float* mc   = (const float*)d_in[9];

    int B    = in_sizes[1];
    int NTR  = in_sizes[3];
    int NTE  = in_sizes[4];
    int NTRX = in_sizes[5] / 2;
    int NTEX = in_sizes[6] / 2;
    int NMC  = in_sizes[9] / (2 * NUM_BINS);
    int nqb  = (NMC + 127) / 128;

    prep_kernel<<<NUM_BINS + 2 + HTR_B + HTE_B + 1, 1024>>>(
        mc, W, bv, trp, tep, trx, tex, y, pred,
        NMC, NTR, NTE, B, NTRX, NTEX);

    dim3 mg(nqb, NUM_BINS, DSPLIT);
    main_kernel<<<mg, 128>>>(bx, y, pred, B);

    dim3 cg(nqb, NUM_BINS);
    combine_kernel<<<cg, 128>>>(NTRX, NTEX, B, NTR, NTE);

    final_kernel<<<1, NUM_BINS * 32>>>((float*)d_out, nqb, NMC, NTE);
}